// round 11
// baseline (speedup 1.0000x reference)
#include <cuda_runtime.h>
#include <cuda_fp16.h>

// FastFood layer, D=1024, R=4, M=16384 rows. One warp per row.
// FWHT_1024 stages commute, so we pick which 5 index bits live in registers at
// each phase. Transposes between phases use hardware ldmatrix.m8n8.x4.trans:
//   image = 16 blocks of 8x8 halves, block stride 144B (4-wf CF for both the
//   STS.128 writes and the LDSM reads).
// Fragment bit map after LDSM.trans (thread t, reg J=4I+s, half e):
//   varying bits V (lane): V&7 = t>>2, V3 = t&1... (V4,V3)=(t1,t0); fixed bits F:
//   F0 = e (half), F>>1 = J.
// Phase plan per r:  x (layout A) -> fwht(ih) -> T1 -> fwht(il) -> gather img
//   -> permuted gather*G -> fwht(jl) -> T2 -> fwht(jh) -> *S -> store.

#define FF_D 1024
#define FF_R 4
#define WPB 8
#define THREADS 256
#define RS_G 40            // gather image halves per row (80B rows)
#define IMG_BYTES 2560     // max(16*144, 32*80)

typedef unsigned long long u64;
typedef unsigned int u32;

__device__ u32  g_bpack[FF_R * 32];   // bit k = signbit(B[r][k*32+l])
__device__ int4 g_pg4[FF_R * 256];    // entry: (slot<<16)|half(G), j = l*32+4q+u
__device__ u32  g_spair[FF_R * 512];  // [r][J*32+t] = half2(S'[64J+jl(t)], S'[64J+32+jl(t)])

__device__ __forceinline__ int jl_of(int t) {
    return (((t >> 1) & 1) << 4) | ((t & 1) << 3) | (t >> 2);
}

__global__ void prep_kernel(const float* __restrict__ B, const float* __restrict__ G,
                            const float* __restrict__ S, const int* __restrict__ P) {
    int t = blockIdx.x * blockDim.x + threadIdx.x;
    int stride = gridDim.x * blockDim.x;
    if (t < FF_R * 32) {
        int r = t >> 5, l = t & 31;
        u32 m = 0;
        #pragma unroll
        for (int k = 0; k < 32; k++)
            m |= (__float_as_uint(B[r * FF_D + k * 32 + l]) >> 31) << k;
        g_bpack[t] = m;
    }
    for (int i = t; i < FF_R * 256; i += stride) {
        int r = i >> 8, rem = i & 255;
        int q = rem >> 5, l = rem & 31;
        int j = r * FF_D + l * 32 + 4 * q;
        u32 e[4];
        #pragma unroll
        for (int u = 0; u < 4; u++) {
            int p = P[j + u];
            u32 slot = (u32)((p >> 5) * RS_G + (p & 31));
            unsigned short gh = __half_as_ushort(__float2half_rn(G[j + u]));
            e[u] = (slot << 16) | (u32)gh;
        }
        g_pg4[i] = make_int4((int)e[0], (int)e[1], (int)e[2], (int)e[3]);
    }
    for (int i = t; i < FF_R * 512; i += stride) {
        int r = i >> 9, rem = i & 511;
        int J = rem >> 5, tt = rem & 31;
        int jl = jl_of(tt);
        float s0 = S[r * FF_D + 64 * J + jl]      * 0.03125f;
        float s1 = S[r * FF_D + 64 * J + 32 + jl] * 0.03125f;
        __half2 h = __floats2half2_rn(s0, s1);
        g_spair[i] = *reinterpret_cast<u32*>(&h);
    }
}

// ---- f32x2 helpers ----
__device__ __forceinline__ u64 pk(float a, float b) {
    u64 u; asm("mov.b64 %0, {%1,%2};" : "=l"(u) : "f"(a), "f"(b)); return u;
}
__device__ __forceinline__ float2 up(u64 u) {
    float2 r; asm("mov.b64 {%0,%1}, %2;" : "=f"(r.x), "=f"(r.y) : "l"(u)); return r;
}
__device__ __forceinline__ u64 swp(u64 v) {
    u64 r;
    asm("{\n\t.reg .b32 a,b;\n\tmov.b64 {a,b}, %1;\n\tmov.b64 %0, {b,a};\n\t}"
        : "=l"(r) : "l"(v));
    return r;
}
__device__ __forceinline__ u64 addx2(u64 a, u64 b) {
    u64 r; asm("add.rn.f32x2 %0, %1, %2;" : "=l"(r) : "l"(a), "l"(b)); return r;
}
__device__ __forceinline__ u64 fmax2(u64 a, u64 b, u64 c) {
    u64 r; asm("fma.rn.f32x2 %0, %1, %2, %3;" : "=l"(r) : "l"(a), "l"(b), "l"(c)); return r;
}
__device__ __forceinline__ u64 mulx2(u64 a, u64 b) {
    u64 r; asm("mul.rn.f32x2 %0, %1, %2;" : "=l"(r) : "l"(a), "l"(b)); return r;
}
#define C_P1M1 0xBF8000003F800000ULL
#define C_M1M1 0xBF800000BF800000ULL

__device__ __forceinline__ u32 h2pack(u64 v) {
    float2 f = up(v);
    __half2 h = __floats2half2_rn(f.x, f.y);
    return *reinterpret_cast<u32*>(&h);
}
__device__ __forceinline__ float2 h2unpack(u32 w) {
    __half2 h = *reinterpret_cast<__half2*>(&w);
    return __half22float2(h);
}

// H32 over {half-bit of each pair} + {4 register-index bits}
__device__ __forceinline__ void fwht2x(u64 va[16]) {
    #pragma unroll
    for (int p = 0; p < 16; p++)
        va[p] = fmax2(va[p], C_P1M1, swp(va[p]));
    #pragma unroll
    for (int m = 1; m <= 8; m <<= 1) {
        #pragma unroll
        for (int p = 0; p < 16; p++) {
            if ((p & m) == 0) {
                u64 a = va[p], b = va[p | m];
                va[p]     = addx2(a, b);
                va[p | m] = fmax2(b, C_M1M1, a);
            }
        }
    }
}

__device__ __forceinline__ void ldsm4t(u32 addr, u32 w[4]) {
    asm volatile("ldmatrix.sync.aligned.m8n8.x4.trans.shared.b16 {%0,%1,%2,%3}, [%4];"
                 : "=r"(w[0]), "=r"(w[1]), "=r"(w[2]), "=r"(w[3]) : "r"(addr));
}

__global__ __launch_bounds__(THREADS, 3)
void fastfood_kernel(const float* __restrict__ x,
                     float* __restrict__ out, int M)
{
    __shared__ __align__(16) char sc[WPB][IMG_BYTES];
    const int warp = threadIdx.x >> 5;
    const int t    = threadIdx.x & 31;
    const int row  = blockIdx.x * WPB + warp;
    if (row >= M) return;
    char* img = sc[warp];
    __half* smh = reinterpret_cast<__half*>(img);
    const u32 imgb = (u32)__cvta_generic_to_shared(img);

    // transpose-image addresses
    const u32 twb    = imgb + (u32)(t >> 1) * 144 + (u32)(t & 1) * 16;   // write base
    const u32 ldsa   = imgb + (u32)(t >> 3) * 144 + (u32)(t & 7) * 16;   // LDSM base (+= 576 per I)
    const int vperm  = jl_of(t);                                          // lane's V-bits value
    char* gw = img + vperm * (RS_G * 2);                                  // gather row (ih = vperm)

    const float* xr = x + (size_t)row * FF_D;

    #pragma unroll 1
    for (int r = 0; r < FF_R; r++) {
        // ---- layout A: thread t holds i = k*32 + t; va[p] = (k=2p, k=2p+1) ----
        const u32 bp = g_bpack[r * 32 + t];
        u64 va[16];
        #pragma unroll
        for (int p = 0; p < 16; p++) {
            u32 m0 = (bp << (31 - 2 * p))     & 0x80000000u;
            u32 m1 = (bp << (31 - 2 * p - 1)) & 0x80000000u;
            float lo = __uint_as_float(__float_as_uint(__ldg(&xr[(2 * p)     * 32 + t])) ^ m0);
            float hi = __uint_as_float(__float_as_uint(__ldg(&xr[(2 * p + 1) * 32 + t])) ^ m1);
            va[p] = pk(lo, hi);
        }
        fwht2x(va);                                   // ih stages

        __syncwarp();                                 // prev r's T2 LDSM reads done
        // ---- T1 write: block t>>1, rows 2m+(t&1), chunk = ih 8m..8m+7 ----
        #pragma unroll
        for (int m = 0; m < 4; m++) {
            uint4 c = make_uint4(h2pack(va[4*m+0]), h2pack(va[4*m+1]),
                                 h2pack(va[4*m+2]), h2pack(va[4*m+3]));
            *reinterpret_cast<uint4*>(img + (twb - imgb) + m * 32) = c;
        }
        __syncwarp();
        // ---- T1 read: LDSM trans -> registers hold il (half = il0, reg J = il>>1) ----
        #pragma unroll
        for (int I = 0; I < 4; I++) {
            u32 w[4];
            ldsm4t(ldsa + (u32)I * 576, w);
            #pragma unroll
            for (int s = 0; s < 4; s++) {
                float2 f = h2unpack(w[s]);
                va[4 * I + s] = pk(f.x, f.y);
            }
        }
        fwht2x(va);                                   // il stages -> h1 complete
        __syncwarp();                                 // LDSM reads done before overwrite

        // ---- gather image: this thread's ih = vperm; halves il = 0..31 in order ----
        #pragma unroll
        for (int m = 0; m < 4; m++) {
            uint4 c = make_uint4(h2pack(va[4*m+0]), h2pack(va[4*m+1]),
                                 h2pack(va[4*m+2]), h2pack(va[4*m+3]));
            *reinterpret_cast<uint4*>(gw + m * 16) = c;
        }
        __syncwarp();
        // ---- permuted gather * G: thread t <- j = t*32 + k' ----
        const int4* PG = g_pg4 + r * 256;
        #pragma unroll
        for (int q = 0; q < 8; q++) {
            int4 pg = __ldg(&PG[q * 32 + t]);
            u32 e0 = (u32)pg.x, e1 = (u32)pg.y, e2 = (u32)pg.z, e3 = (u32)pg.w;
            float t0 = __half2float(smh[e0 >> 16]);
            float t1 = __half2float(smh[e1 >> 16]);
            float t2 = __half2float(smh[e2 >> 16]);
            float t3 = __half2float(smh[e3 >> 16]);
            float g0 = __half2float(__ushort_as_half((unsigned short)(e0 & 0xffffu)));
            float g1 = __half2float(__ushort_as_half((unsigned short)(e1 & 0xffffu)));
            float g2 = __half2float(__ushort_as_half((unsigned short)(e2 & 0xffffu)));
            float g3 = __half2float(__ushort_as_half((unsigned short)(e3 & 0xffffu)));
            va[2 * q]     = mulx2(pk(t0, t1), pk(g0, g1));
            va[2 * q + 1] = mulx2(pk(t2, t3), pk(g2, g3));
        }
        __syncwarp();                                 // gather reads done before T2 writes
        fwht2x(va);                                   // jl stages

        // ---- T2 write: block t>>1 (jh = t), rows 2m+(t&1), chunk jl 8m..8m+7 ----
        #pragma unroll
        for (int m = 0; m < 4; m++) {
            uint4 c = make_uint4(h2pack(va[4*m+0]), h2pack(va[4*m+1]),
                                 h2pack(va[4*m+2]), h2pack(va[4*m+3]));
            *reinterpret_cast<uint4*>(img + (twb - imgb) + m * 32) = c;
        }
        __syncwarp();
        // ---- T2 read: registers hold jh (half = jh0, reg J = jh>>1); lanes = jl ----
        #pragma unroll
        for (int I = 0; I < 4; I++) {
            u32 w[4];
            ldsm4t(ldsa + (u32)I * 576, w);
            #pragma unroll
            for (int s = 0; s < 4; s++) {
                float2 f = h2unpack(w[s]);
                va[4 * I + s] = pk(f.x, f.y);
            }
        }
        fwht2x(va);                                   // jh stages -> h2 complete

        // ---- *S + store: va[J] = (j = 64J + jl(t), j + 32) ----
        const u32* Sp = g_spair + r * 512;
        float* o = out + (size_t)row * (FF_R * FF_D) + r * FF_D;
        #pragma unroll
        for (int J = 0; J < 16; J++) {
            float2 s = h2unpack(__ldg(&Sp[J * 32 + t]));
            float2 f = up(va[J]);
            o[64 * J + vperm]      = f.x * s.x;
            o[64 * J + 32 + vperm] = f.y * s.y;
        }
    }
}

extern "C" void kernel_launch(void* const* d_in, const int* in_sizes, int n_in,
                              void* d_out, int out_size) {
    const float* x = (const float*)d_in[0];   // (4,512,8,1024) fp32
    const float* B = (const float*)d_in[1];   // (4,1024) fp32
    const float* G = (const float*)d_in[2];   // (4,1024) fp32
    const float* S = (const float*)d_in[3];   // (4,1024) fp32
    const int*   P = (const int*)  d_in[4];   // (4,1024) int32
    float* out = (float*)d_out;

    const int M = in_sizes[0] / FF_D;         // 16384 rows
    prep_kernel<<<32, 256>>>(B, G, S, P);
    const int blocks = (M + WPB - 1) / WPB;
    fastfood_kernel<<<blocks, THREADS>>>(x, out, M);
}

// round 12
// speedup vs baseline: 1.0343x; 1.0343x over previous
#include <cuda_runtime.h>
#include <cuda_fp16.h>

// FastFood layer, D=1024, R=4, M=16384 rows. One warp per row. Zero shuffles.
// R10 structure (fp16 smem image, f32x2 register-pair butterflies) with
// conflict-free 68-byte image rows:
//   image = 32 rows x 34 halves (17 words). Row side = 16 scalar word ops,
//   banks 17*l + w, 17 invertible mod 32 -> CF. Column side = 32 scalar half
//   ops, lane pairs merge into 16 words on distinct banks -> CF.
// half-slot(i) = (i>>5)*34 + (i&31).
// Layouts: A: idx = k*32 + l   B: idx = l*32 + k  (k = reg-pair halves, l = lane)

#define FF_D 1024
#define FF_R 4
#define WPB 8
#define THREADS (WPB * 32)
#define RSH 34   // halves per image row
#define RSW 17   // words per image row

typedef unsigned long long u64;
typedef unsigned int u32;

__device__ u32  g_bpack[FF_R * 32];   // bit k = signbit(B[r][k*32+l])
__device__ int4 g_pg4[FF_R * 256];    // [r][q*32+l]: entries for j = l*32+4q+{0..3}
__device__ u32  g_sh2[FF_R * 512];    // [r][p*32+l] = half2(S'[2p*32+l], S'[(2p+1)*32+l])

__global__ void prep_kernel(const float* __restrict__ B, const float* __restrict__ G,
                            const float* __restrict__ S, const int* __restrict__ P) {
    int t = blockIdx.x * blockDim.x + threadIdx.x;
    int stride = gridDim.x * blockDim.x;
    if (t < FF_R * 32) {
        int r = t >> 5, l = t & 31;
        u32 m = 0;
        #pragma unroll
        for (int k = 0; k < 32; k++)
            m |= (__float_as_uint(B[r * FF_D + k * 32 + l]) >> 31) << k;
        g_bpack[t] = m;
    }
    for (int i = t; i < FF_R * 256; i += stride) {
        int r = i >> 8, rem = i & 255;
        int q = rem >> 5, l = rem & 31;
        int j = r * FF_D + l * 32 + 4 * q;
        u32 e[4];
        #pragma unroll
        for (int u = 0; u < 4; u++) {
            int p = P[j + u];
            u32 slot = (u32)((p >> 5) * RSH + (p & 31));   // half-slot
            unsigned short gh = __half_as_ushort(__float2half_rn(G[j + u]));
            e[u] = (slot << 16) | (u32)gh;
        }
        g_pg4[i] = make_int4((int)e[0], (int)e[1], (int)e[2], (int)e[3]);
    }
    for (int i = t; i < FF_R * 512; i += stride) {
        int r = i >> 9, rem = i & 511;
        int p = rem >> 5, l = rem & 31;
        float s0 = S[r * FF_D + (2 * p)     * 32 + l] * 0.03125f;
        float s1 = S[r * FF_D + (2 * p + 1) * 32 + l] * 0.03125f;
        __half2 h = __floats2half2_rn(s0, s1);
        g_sh2[i] = *reinterpret_cast<u32*>(&h);
    }
}

// ---- f32x2 helpers ----
__device__ __forceinline__ u64 pk(float a, float b) {
    u64 u; asm("mov.b64 %0, {%1,%2};" : "=l"(u) : "f"(a), "f"(b)); return u;
}
__device__ __forceinline__ float2 up(u64 u) {
    float2 r; asm("mov.b64 {%0,%1}, %2;" : "=f"(r.x), "=f"(r.y) : "l"(u)); return r;
}
__device__ __forceinline__ u64 swp(u64 v) {
    u64 r;
    asm("{\n\t.reg .b32 a,b;\n\tmov.b64 {a,b}, %1;\n\tmov.b64 %0, {b,a};\n\t}"
        : "=l"(r) : "l"(v));
    return r;
}
__device__ __forceinline__ u64 addx2(u64 a, u64 b) {
    u64 r; asm("add.rn.f32x2 %0, %1, %2;" : "=l"(r) : "l"(a), "l"(b)); return r;
}
__device__ __forceinline__ u64 fmax2(u64 a, u64 b, u64 c) {   // a*b + c
    u64 r; asm("fma.rn.f32x2 %0, %1, %2, %3;" : "=l"(r) : "l"(a), "l"(b), "l"(c)); return r;
}
__device__ __forceinline__ u64 mulx2(u64 a, u64 b) {
    u64 r; asm("mul.rn.f32x2 %0, %1, %2;" : "=l"(r) : "l"(a), "l"(b)); return r;
}
#define C_P1M1 0xBF8000003F800000ULL   // {+1.0, -1.0}
#define C_M1M1 0xBF800000BF800000ULL   // {-1.0, -1.0}

__device__ __forceinline__ u32 h2pack(u64 v) {
    float2 f = up(v);
    __half2 h = __floats2half2_rn(f.x, f.y);
    return *reinterpret_cast<u32*>(&h);
}
__device__ __forceinline__ float2 h2unpack(u32 w) {
    __half2 h = *reinterpret_cast<__half2*>(&w);
    return __half22float2(h);
}

// H32 over {half-bit of each pair} + {4 register-pair index bits}
__device__ __forceinline__ void fwht2x(u64 va[16]) {
    #pragma unroll
    for (int p = 0; p < 16; p++)
        va[p] = fmax2(va[p], C_P1M1, swp(va[p]));
    #pragma unroll
    for (int m = 1; m <= 8; m <<= 1) {
        #pragma unroll
        for (int p = 0; p < 16; p++) {
            if ((p & m) == 0) {
                u64 a = va[p], b = va[p | m];
                va[p]     = addx2(a, b);
                va[p | m] = fmax2(b, C_M1M1, a);
            }
        }
    }
}

__global__ __launch_bounds__(THREADS, 4)
void fastfood_kernel(const float* __restrict__ x,
                     float* __restrict__ out, int M)
{
    __shared__ u32 sc[WPB][32 * RSW];              // 2176 B per warp image
    const int warp = threadIdx.x >> 5;
    const int t    = threadIdx.x & 31;             // lane
    const int row  = blockIdx.x * WPB + warp;
    if (row >= M) return;
    u32*    sm32 = sc[warp];
    __half* smh  = reinterpret_cast<__half*>(sm32);
    const float* xr = x + (size_t)row * FF_D;

    #pragma unroll 1
    for (int r = 0; r < FF_R; r++) {
        // ---- v = x * B[r] (sign-bit xor), layout A: va[p] = (k=2p, k=2p+1) ----
        const u32 bp = g_bpack[r * 32 + t];
        u64 va[16];
        #pragma unroll
        for (int p = 0; p < 16; p++) {
            u32 m0 = (bp << (31 - 2 * p))     & 0x80000000u;
            u32 m1 = (bp << (31 - 2 * p - 1)) & 0x80000000u;
            float lo = __uint_as_float(__float_as_uint(__ldg(&xr[(2 * p)     * 32 + t])) ^ m0);
            float hi = __uint_as_float(__float_as_uint(__ldg(&xr[(2 * p + 1) * 32 + t])) ^ m1);
            va[p] = pk(lo, hi);
        }

        // ---- FWHT #1: high bits (layout A) ----
        fwht2x(va);
        // T1 write: value (k, t) -> row k, offset t. Column side: CF (pair-merge).
        // (prev iter's T2 reads used this thread's identical address set: no sync)
        #pragma unroll
        for (int p = 0; p < 16; p++) {
            float2 f = up(va[p]);
            smh[(2 * p)     * RSH + t] = __float2half_rn(f.x);
            smh[(2 * p + 1) * RSH + t] = __float2half_rn(f.y);
        }
        __syncwarp();
        // T1 read: own row l = t, words w -> halves (k'=2w, 2w+1). CF (17 invertible).
        #pragma unroll
        for (int w = 0; w < 16; w++) {
            float2 f = h2unpack(sm32[t * RSW + w]);
            va[w] = pk(f.x, f.y);
        }
        // ---- FWHT #1: low bits (layout B) -> h1 ----
        fwht2x(va);

        // ---- gather image: own-row word writes (only this thread read row t: no sync) ----
        #pragma unroll
        for (int w = 0; w < 16; w++)
            sm32[t * RSW + w] = h2pack(va[w]);
        __syncwarp();
        // ---- permuted gather * G: thread t <- j = t*32 + 4q + u ----
        const int4* PG = g_pg4 + r * 256;
        #pragma unroll
        for (int q = 0; q < 8; q++) {
            int4 pg = __ldg(&PG[q * 32 + t]);
            u32 e0 = (u32)pg.x, e1 = (u32)pg.y, e2 = (u32)pg.z, e3 = (u32)pg.w;
            float t0 = __half2float(smh[e0 >> 16]);
            float t1 = __half2float(smh[e1 >> 16]);
            float t2 = __half2float(smh[e2 >> 16]);
            float t3 = __half2float(smh[e3 >> 16]);
            float g0 = __half2float(__ushort_as_half((unsigned short)(e0 & 0xffffu)));
            float g1 = __half2float(__ushort_as_half((unsigned short)(e1 & 0xffffu)));
            float g2 = __half2float(__ushort_as_half((unsigned short)(e2 & 0xffffu)));
            float g3 = __half2float(__ushort_as_half((unsigned short)(e3 & 0xffffu)));
            va[2 * q]     = mulx2(pk(t0, t1), pk(g0, g1));
            va[2 * q + 1] = mulx2(pk(t2, t3), pk(g2, g3));
        }
        __syncwarp();                                   // all gathers done before overwrite

        // ---- FWHT #2: low bits (layout B) ----
        fwht2x(va);
        // T2 write: own-row word writes. CF.
        #pragma unroll
        for (int w = 0; w < 16; w++)
            sm32[t * RSW + w] = h2pack(va[w]);
        __syncwarp();
        // T2 read: column side, value j = k*32 + t from row k offset t. CF (pair-merge).
        #pragma unroll
        for (int p = 0; p < 16; p++) {
            float f0 = __half2float(smh[(2 * p)     * RSH + t]);
            float f1 = __half2float(smh[(2 * p + 1) * RSH + t]);
            va[p] = pk(f0, f1);
        }
        // ---- FWHT #2: high bits (layout A) ----
        fwht2x(va);

        // ---- scale (half2-paired prescaled S) + coalesced store ----
        const u32* Sh = g_sh2 + r * 512;
        float* o = out + (size_t)row * (FF_R * FF_D) + r * FF_D;
        #pragma unroll
        for (int p = 0; p < 16; p++) {
            float2 s = h2unpack(__ldg(&Sh[p * 32 + t]));
            float2 f = up(mulx2(va[p], pk(s.x, s.y)));
            o[(2 * p)     * 32 + t] = f.x;
            o[(2 * p + 1) * 32 + t] = f.y;
        }
    }
}

extern "C" void kernel_launch(void* const* d_in, const int* in_sizes, int n_in,
                              void* d_out, int out_size) {
    const float* x = (const float*)d_in[0];   // (4,512,8,1024) fp32
    const float* B = (const float*)d_in[1];   // (4,1024) fp32
    const float* G = (const float*)d_in[2];   // (4,1024) fp32
    const float* S = (const float*)d_in[3];   // (4,1024) fp32
    const int*   P = (const int*)  d_in[4];   // (4,1024) int32
    float* out = (float*)d_out;

    const int M = in_sizes[0] / FF_D;         // 16384 rows
    prep_kernel<<<32, 256>>>(B, G, S, P);
    const int blocks = (M + WPB - 1) / WPB;
    fastfood_kernel<<<blocks, THREADS>>>(x, out, M);
}